// round 1
// baseline (speedup 1.0000x reference)
#include <cuda_runtime.h>
#include <math.h>

#define JN 24
#define EPSF 1e-8f

// Skeleton: parents (compile-time), DFS pre-order to minimize live registers.
// PARENTS = [-1,0,0,0,1,2,3,4,5,6,7,8,9,9,9,12,13,14,16,17,18,19,20,21]
// DFS:      0,1,4,7,10, 2,5,8,11, 3,6,9,12,15, 13,16,18,20,22, 14,17,19,21,23

__global__ __launch_bounds__(256) void fk_kernel(
    const float4* __restrict__ rootq,   // [B,4]  (w,x,y,z)
    const float*  __restrict__ rootp,   // [B,3]
    const float4* __restrict__ localq,  // [B,J,4]
    const float*  __restrict__ bl,      // [B,J]
    const float*  __restrict__ restd,   // [J,3]
    float*        __restrict__ out,     // [B,J,3]
    int nbatch)
{
    __shared__ float sdir[JN * 3];
    if (threadIdx.x < JN * 3) sdir[threadIdx.x] = restd[threadIdx.x];
    __syncthreads();

    int b = blockIdx.x * blockDim.x + threadIdx.x;
    if (b >= nbatch) return;

    const int PAR[JN]   = {-1,0,0,0,1,2,3,4,5,6,7,8,9,9,9,12,13,14,16,17,18,19,20,21};
    const int ORDER[JN] = {0,1,4,7,10,2,5,8,11,3,6,9,12,15,13,16,18,20,22,14,17,19,21,23};

    // Per-joint state; after full unroll with constant indices these become
    // individual SSA values and dead ones are eliminated (DFS order keeps the
    // simultaneously-live set to <= 4 joints).
    float gqw[JN], gqx[JN], gqy[JN], gqz[JN];
    float gpx[JN], gpy[JN], gpz[JN];

    // Root: normalize orientation quat, position passes through.
    {
        float4 rq = rootq[b];
        float s   = rq.x*rq.x + rq.y*rq.y + rq.z*rq.z + rq.w*rq.w;
        float inv = 1.0f / (sqrtf(s) + EPSF);
        gqw[0] = rq.x * inv;
        gqx[0] = rq.y * inv;
        gqy[0] = rq.z * inv;
        gqz[0] = rq.w * inv;
    }
    gpx[0] = rootp[3 * b + 0];
    gpy[0] = rootp[3 * b + 1];
    gpz[0] = rootp[3 * b + 2];

    float* o = out + (size_t)b * (JN * 3);
    o[0] = gpx[0];
    o[1] = gpy[0];
    o[2] = gpz[0];

    const float4* lq  = localq + (size_t)b * JN;
    const float*  blb = bl     + (size_t)b * JN;

    #pragma unroll
    for (int i = 1; i < JN; i++) {
        const int j = ORDER[i];
        const int p = PAR[j];

        // Normalize local quat for joint j.
        float4 c4 = lq[j];
        float s   = c4.x*c4.x + c4.y*c4.y + c4.z*c4.z + c4.w*c4.w;
        float inv = 1.0f / (sqrtf(s) + EPSF);
        float cw = c4.x * inv, cx = c4.y * inv, cy = c4.z * inv, cz = c4.w * inv;

        // Parent global quat.
        float pw = gqw[p], px = gqx[p], py = gqy[p], pz = gqz[p];

        // Global quat for j = parent ∘ local.
        gqw[j] = pw*cw - px*cx - py*cy - pz*cz;
        gqx[j] = pw*cx + px*cw + py*cz - pz*cy;
        gqy[j] = pw*cy - px*cz + py*cw + pz*cx;
        gqz[j] = pw*cz + px*cy - py*cx + pz*cw;

        // Rotate rest direction d[j] by the PARENT quat:
        // t = 2*cross(qvec, d); r = d + qw*t + cross(qvec, t)
        float dx = sdir[3*j + 0], dy = sdir[3*j + 1], dz = sdir[3*j + 2];
        float tx = 2.0f * (py*dz - pz*dy);
        float ty = 2.0f * (pz*dx - px*dz);
        float tz = 2.0f * (px*dy - py*dx);
        float rx = dx + pw*tx + (py*tz - pz*ty);
        float ry = dy + pw*ty + (pz*tx - px*tz);
        float rz = dz + pw*tz + (px*ty - py*tx);

        float L = blb[j];
        gpx[j] = gpx[p] + rx * L;
        gpy[j] = gpy[p] + ry * L;
        gpz[j] = gpz[p] + rz * L;

        o[3*j + 0] = gpx[j];
        o[3*j + 1] = gpy[j];
        o[3*j + 2] = gpz[j];
    }
}

extern "C" void kernel_launch(void* const* d_in, const int* in_sizes, int n_in,
                              void* d_out, int out_size)
{
    // metadata order: root_orientation_quat [B,4], root_position [B,3],
    //                 local_joint_rotations_quat [B,J,4], bone_lengths [B,J],
    //                 rest_directions [J,3]
    const float4* rootq  = (const float4*)d_in[0];
    const float*  rootp  = (const float*)d_in[1];
    const float4* localq = (const float4*)d_in[2];
    const float*  bl     = (const float*)d_in[3];
    const float*  restd  = (const float*)d_in[4];
    float*        out    = (float*)d_out;

    int nbatch = in_sizes[1] / 3;   // root_position has B*3 elements

    const int threads = 256;
    int blocks = (nbatch + threads - 1) / threads;
    fk_kernel<<<blocks, threads>>>(rootq, rootp, localq, bl, restd, out, nbatch);
}

// round 3
// speedup vs baseline: 1.4617x; 1.4617x over previous
#include <cuda_runtime.h>
#include <math.h>

#define JN 24
#define EPSF 1e-8f
#define TPB 128
#define ROW 73   // padded row stride (floats); 73 mod 32 = 9, gcd(9,32)=1 -> conflict-free

// Skeleton: parents (compile-time), DFS pre-order to minimize live registers.
// PARENTS = [-1,0,0,0,1,2,3,4,5,6,7,8,9,9,9,12,13,14,16,17,18,19,20,21]
// DFS:      0,1,4,7,10, 2,5,8,11, 3,6,9,12,15, 13,16,18,20,22, 14,17,19,21,23

__global__ __launch_bounds__(TPB) void fk_kernel(
    const float4* __restrict__ rootq,   // [B,4]  (w,x,y,z)
    const float*  __restrict__ rootp,   // [B,3]
    const float4* __restrict__ localq,  // [B,J,4]
    const float*  __restrict__ bl,      // [B,J]
    const float*  __restrict__ restd,   // [J,3]
    float*        __restrict__ out,     // [B,J,3]
    int nbatch)
{
    __shared__ float sdir[JN * 3];
    __shared__ float so[TPB * ROW];     // per-thread output staging, padded rows

    if (threadIdx.x < JN * 3) sdir[threadIdx.x] = restd[threadIdx.x];
    __syncthreads();

    const int tid = threadIdx.x;
    const int b   = blockIdx.x * TPB + tid;
    const bool active = (b < nbatch);

    if (active) {
        const int PAR[JN]   = {-1,0,0,0,1,2,3,4,5,6,7,8,9,9,9,12,13,14,16,17,18,19,20,21};
        const int ORDER[JN] = {0,1,4,7,10,2,5,8,11,3,6,9,12,15,13,16,18,20,22,14,17,19,21,23};

        float gqw[JN], gqx[JN], gqy[JN], gqz[JN];
        float gpx[JN], gpy[JN], gpz[JN];

        // Root: normalize orientation quat; position passes through.
        {
            float4 rq = rootq[b];
            float s   = rq.x*rq.x + rq.y*rq.y + rq.z*rq.z + rq.w*rq.w;
            float inv = 1.0f / (sqrtf(s) + EPSF);
            gqw[0] = rq.x * inv;
            gqx[0] = rq.y * inv;
            gqy[0] = rq.z * inv;
            gqz[0] = rq.w * inv;
        }
        gpx[0] = rootp[3 * b + 0];
        gpy[0] = rootp[3 * b + 1];
        gpz[0] = rootp[3 * b + 2];

        float* srow = so + tid * ROW;
        srow[0] = gpx[0];
        srow[1] = gpy[0];
        srow[2] = gpz[0];

        const float4* lq  = localq + (size_t)b * JN;
        const float*  blb = bl     + (size_t)b * JN;

        #pragma unroll
        for (int i = 1; i < JN; i++) {
            const int j = ORDER[i];
            const int p = PAR[j];

            // Normalize local quat for joint j.
            float4 c4 = lq[j];
            float s   = c4.x*c4.x + c4.y*c4.y + c4.z*c4.z + c4.w*c4.w;
            float inv = 1.0f / (sqrtf(s) + EPSF);
            float cw = c4.x * inv, cx = c4.y * inv, cy = c4.z * inv, cz = c4.w * inv;

            // Parent global quat.
            float pw = gqw[p], px = gqx[p], py = gqy[p], pz = gqz[p];

            // Global quat for j = parent ∘ local.
            gqw[j] = pw*cw - px*cx - py*cy - pz*cz;
            gqx[j] = pw*cx + px*cw + py*cz - pz*cy;
            gqy[j] = pw*cy - px*cz + py*cw + pz*cx;
            gqz[j] = pw*cz + px*cy - py*cx + pz*cw;

            // Rotate rest direction d[j] by the PARENT quat:
            // t = 2*cross(qvec, d); r = d + qw*t + cross(qvec, t)
            float dx = sdir[3*j + 0], dy = sdir[3*j + 1], dz = sdir[3*j + 2];
            float tx = 2.0f * (py*dz - pz*dy);
            float ty = 2.0f * (pz*dx - px*dz);
            float tz = 2.0f * (px*dy - py*dx);
            float rx = dx + pw*tx + (py*tz - pz*ty);
            float ry = dy + pw*ty + (pz*tx - px*tz);
            float rz = dz + pw*tz + (px*ty - py*tx);

            float L = blb[j];
            gpx[j] = gpx[p] + rx * L;
            gpy[j] = gpy[p] + ry * L;
            gpz[j] = gpz[p] + rz * L;

            srow[3*j + 0] = gpx[j];
            srow[3*j + 1] = gpy[j];
            srow[3*j + 2] = gpz[j];
        }
    }
    __syncthreads();

    // Coalesced copy: block's output region is contiguous [TPB * 72] floats.
    // Emit float4 stores (16B per thread, consecutive threads -> consecutive
    // 16B) so every 32B sector is fully written (no write-allocate reads).
    {
        const size_t block_word0 = (size_t)blockIdx.x * TPB * (JN * 3);
        const size_t total_words = (size_t)nbatch * (JN * 3);
        float4* out4 = (float4*)out;

        #pragma unroll
        for (int i = tid; i < TPB * 18; i += TPB) {       // 18 float4 per element
            int elem = i / 18;
            int w    = (i - elem * 18) * 4;
            size_t gw = block_word0 + (size_t)i * 4;
            if (gw < total_words) {
                float4 v;
                v.x = so[elem * ROW + w + 0];
                v.y = so[elem * ROW + w + 1];
                v.z = so[elem * ROW + w + 2];
                v.w = so[elem * ROW + w + 3];
                out4[gw / 4] = v;
            }
        }
    }
}

extern "C" void kernel_launch(void* const* d_in, const int* in_sizes, int n_in,
                              void* d_out, int out_size)
{
    // metadata order: root_orientation_quat [B,4], root_position [B,3],
    //                 local_joint_rotations_quat [B,J,4], bone_lengths [B,J],
    //                 rest_directions [J,3]
    const float4* rootq  = (const float4*)d_in[0];
    const float*  rootp  = (const float*)d_in[1];
    const float4* localq = (const float4*)d_in[2];
    const float*  bl     = (const float*)d_in[3];
    const float*  restd  = (const float*)d_in[4];
    float*        out    = (float*)d_out;

    int nbatch = in_sizes[1] / 3;   // root_position has B*3 elements

    int blocks = (nbatch + TPB - 1) / TPB;
    fk_kernel<<<blocks, TPB>>>(rootq, rootp, localq, bl, restd, out, nbatch);
}

// round 4
// speedup vs baseline: 2.7727x; 1.8969x over previous
#include <cuda_runtime.h>
#include <math.h>

#define JN 24
#define EPSF 1e-8f
#define TPB 256

// PARENTS is monotone (parent < child), so natural order 0..23 is a valid
// traversal AND produces the output floats (3j..3j+2) strictly sequentially.
// A 4-float rolling register buffer turns the per-thread output stream into
// 18 consecutive STG.128s -> full sector coverage after L2 merge, no smem
// staging, so occupancy is register-bound (~60%) instead of smem-bound (37%).

__global__ __launch_bounds__(TPB) void fk_kernel(
    const float4* __restrict__ rootq,   // [B,4]  (w,x,y,z)
    const float*  __restrict__ rootp,   // [B,3]
    const float4* __restrict__ localq,  // [B,J,4]
    const float*  __restrict__ bl,      // [B,J]
    const float*  __restrict__ restd,   // [J,3]
    float*        __restrict__ out,     // [B,J,3]
    int nbatch)
{
    __shared__ float sdir[JN * 3];
    if (threadIdx.x < JN * 3) sdir[threadIdx.x] = restd[threadIdx.x];
    __syncthreads();

    const int b = blockIdx.x * TPB + threadIdx.x;
    if (b >= nbatch) return;

    const int PAR[JN] = {-1,0,0,0,1,2,3,4,5,6,7,8,9,9,9,12,13,14,16,17,18,19,20,21};

    // Hoist all 24 bone lengths as 6 independent float4 loads (MLP).
    float blv[JN];
    {
        const float4* bl4 = (const float4*)(bl + (size_t)b * JN);
        #pragma unroll
        for (int i = 0; i < 6; i++) {
            float4 v = bl4[i];
            blv[4*i + 0] = v.x; blv[4*i + 1] = v.y;
            blv[4*i + 2] = v.z; blv[4*i + 3] = v.w;
        }
    }

    float gqw[JN], gqx[JN], gqy[JN], gqz[JN];
    float gpx[JN], gpy[JN], gpz[JN];

    // Root: normalize orientation quat; position passes through.
    {
        float4 rq = rootq[b];
        float s   = rq.x*rq.x + rq.y*rq.y + rq.z*rq.z + rq.w*rq.w;
        float inv = 1.0f / (sqrtf(s) + EPSF);
        gqw[0] = rq.x * inv;
        gqx[0] = rq.y * inv;
        gqy[0] = rq.z * inv;
        gqz[0] = rq.w * inv;
    }
    gpx[0] = rootp[3 * b + 0];
    gpy[0] = rootp[3 * b + 1];
    gpz[0] = rootp[3 * b + 2];

    // Rolling 4-float output buffer -> STG.128 per 4 completed floats.
    float sb[4];
    float4* out4 = (float4*)out + (size_t)b * 18;

    #define EMIT(o, v)                                                   \
        do {                                                             \
            sb[(o) & 3] = (v);                                           \
            if (((o) & 3) == 3)                                          \
                out4[(o) >> 2] = make_float4(sb[0], sb[1], sb[2], sb[3]);\
        } while (0)

    EMIT(0, gpx[0]);
    EMIT(1, gpy[0]);
    EMIT(2, gpz[0]);

    const float4* lq = localq + (size_t)b * JN;

    #pragma unroll
    for (int j = 1; j < JN; j++) {
        const int p = PAR[j];

        // Normalize local quat for joint j.
        float4 c4 = lq[j];
        float s   = c4.x*c4.x + c4.y*c4.y + c4.z*c4.z + c4.w*c4.w;
        float inv = 1.0f / (sqrtf(s) + EPSF);
        float cw = c4.x * inv, cx = c4.y * inv, cy = c4.z * inv, cz = c4.w * inv;

        // Parent global quat.
        float pw = gqw[p], px = gqx[p], py = gqy[p], pz = gqz[p];

        // Global quat for j = parent . local.
        gqw[j] = pw*cw - px*cx - py*cy - pz*cz;
        gqx[j] = pw*cx + px*cw + py*cz - pz*cy;
        gqy[j] = pw*cy - px*cz + py*cw + pz*cx;
        gqz[j] = pw*cz + px*cy - py*cx + pz*cw;

        // Rotate rest direction d[j] by the PARENT quat:
        // t = 2*cross(qvec, d); r = d + qw*t + cross(qvec, t)
        float dx = sdir[3*j + 0], dy = sdir[3*j + 1], dz = sdir[3*j + 2];
        float tx = 2.0f * (py*dz - pz*dy);
        float ty = 2.0f * (pz*dx - px*dz);
        float tz = 2.0f * (px*dy - py*dx);
        float rx = dx + pw*tx + (py*tz - pz*ty);
        float ry = dy + pw*ty + (pz*tx - px*tz);
        float rz = dz + pw*tz + (px*ty - py*tx);

        float L = blv[j];
        gpx[j] = gpx[p] + rx * L;
        gpy[j] = gpy[p] + ry * L;
        gpz[j] = gpz[p] + rz * L;

        EMIT(3*j + 0, gpx[j]);
        EMIT(3*j + 1, gpy[j]);
        EMIT(3*j + 2, gpz[j]);
    }
    #undef EMIT
}

extern "C" void kernel_launch(void* const* d_in, const int* in_sizes, int n_in,
                              void* d_out, int out_size)
{
    // metadata order: root_orientation_quat [B,4], root_position [B,3],
    //                 local_joint_rotations_quat [B,J,4], bone_lengths [B,J],
    //                 rest_directions [J,3]
    const float4* rootq  = (const float4*)d_in[0];
    const float*  rootp  = (const float*)d_in[1];
    const float4* localq = (const float4*)d_in[2];
    const float*  bl     = (const float*)d_in[3];
    const float*  restd  = (const float*)d_in[4];
    float*        out    = (float*)d_out;

    int nbatch = in_sizes[1] / 3;   // root_position has B*3 elements

    int blocks = (nbatch + TPB - 1) / TPB;
    fk_kernel<<<blocks, TPB>>>(rootq, rootp, localq, bl, restd, out, nbatch);
}